// round 15
// baseline (speedup 1.0000x reference)
#include <cuda_runtime.h>
#include <cuda_fp16.h>
#include <math.h>
#include <stdint.h>

#define BATCH 4096
#define DIM   768
#define NCLS  10

#define BM 128
#define BN 256
#define BK 64                 // 64 halves = 128B per row-chunk
#define NKIT (DIM / BK)       // 12
#define NCTA_TAML 272
#define NARRIVE (NCTA_TAML + 1)
#define NCE_BLK (BATCH / 8)   // 512
#define NPART 16
#define NCS_BLK (3 * NPART)   // 48
#define ROWS_PER_PART (BATCH / NPART)  // 256

// 3-stage smem pipeline: each stage = A(16KB) + B(32KB) = 48KB
#define STAGE_BYTES 49152
#define OFF_MISC (3 * STAGE_BYTES)
#define OFF_STHR (OFF_MISC)
#define OFF_LROW (OFF_MISC + 512)
#define OFF_LCOL (OFF_MISC + 1024)
#define OFF_WRED (OFF_MISC + 2048)
#define OFF_LAST (OFF_MISC + 2088)     // int flag: am I the last block?
#define DYN_SMEM (OFF_MISC + 2112)     // 149568

// tals-block layout inside the same dynamic smem
#define TOFF_SC   0
#define TOFF_ED   30720
#define TOFF_WCNT 31232
#define TOFF_CNTS 31616

__device__ __forceinline__ int clampc(int v) {
    return v < 0 ? 0 : (v >= NCLS ? NCLS - 1 : v);
}
__device__ __forceinline__ uint32_t s2u(const void* p) {
    uint32_t a;
    asm("{ .reg .u64 t; cvta.to.shared.u64 t, %1; cvt.u32.u64 %0, t; }" : "=r"(a) : "l"(p));
    return a;
}
__device__ __forceinline__ uint32_t h2u(__half2 h) {
    return *reinterpret_cast<uint32_t*>(&h);
}

#define LDSM4(r0, r1, r2, r3, addr) \
    asm volatile("ldmatrix.sync.aligned.m8n8.x4.shared.b16 {%0,%1,%2,%3}, [%4];" \
                 : "=r"(r0), "=r"(r1), "=r"(r2), "=r"(r3) : "r"(addr))

#define MMA_F16(d, a, b0, b1) \
    asm volatile("mma.sync.aligned.m16n8k16.row.col.f32.f16.f16.f32 " \
                 "{%0,%1,%2,%3},{%4,%5,%6,%7},{%8,%9},{%0,%1,%2,%3};" \
                 : "+f"((d)[0]), "+f"((d)[1]), "+f"((d)[2]), "+f"((d)[3]) \
                 : "r"((a)[0]), "r"((a)[1]), "r"((a)[2]), "r"((a)[3]), \
                   "r"(b0), "r"(b1))

#define CPA16(dst, src) \
    asm volatile("cp.async.cg.shared.global [%0], [%1], 16;" :: "r"(dst), "l"(src) : "memory")
#define CPCOMMIT() asm volatile("cp.async.commit_group;" ::: "memory")
#define CPWAIT(n)  asm volatile("cp.async.wait_group %0;" :: "n"(n) : "memory")

// ---------------- scratch ----------------
__device__ __half g_enorm[BATCH * DIM];
__device__ float g_cents[NCLS * DIM];
__device__ float g_ce_part[NCE_BLK];
__device__ float g_taml_part[NCTA_TAML];
__device__ float g_tals;
__device__ float g_nvalid;
__device__ int   g_arrive;            // zero-initialized; reset to 0 by last block

// ---------------- CE + row normalization (+ block 0 zeroes g_cents) --------
__global__ __launch_bounds__(256) void k_ce_norm(
    const float* __restrict__ logits,
    const int* __restrict__ labels,
    const float* __restrict__ emb)
{
    __shared__ float wce[8];
    const unsigned FULL = 0xffffffffu;
    int warp = threadIdx.x >> 5;
    int lane = threadIdx.x & 31;
    int row  = blockIdx.x * 8 + warp;

    if (blockIdx.x == 0) {
        for (int i = threadIdx.x; i < NCLS * DIM; i += 256) g_cents[i] = 0.0f;
    }

    const float4* e4 = (const float4*)(emb + (size_t)row * DIM);
    float4 v[6];
    float ss = 0.0f;
#pragma unroll
    for (int c = 0; c < 3; c++) {
        v[2 * c]     = e4[c * 64 + lane * 2];
        v[2 * c + 1] = e4[c * 64 + lane * 2 + 1];
        ss += v[2*c].x * v[2*c].x + v[2*c].y * v[2*c].y
            + v[2*c].z * v[2*c].z + v[2*c].w * v[2*c].w
            + v[2*c+1].x * v[2*c+1].x + v[2*c+1].y * v[2*c+1].y
            + v[2*c+1].z * v[2*c+1].z + v[2*c+1].w * v[2*c+1].w;
    }
#pragma unroll
    for (int o = 16; o; o >>= 1) ss += __shfl_xor_sync(FULL, ss, o);
    float inv = 1.0f / fmaxf(sqrtf(ss), 1e-12f);

    uint4* o16 = (uint4*)(g_enorm + (size_t)row * DIM);
#pragma unroll
    for (int c = 0; c < 3; c++) {
        uint4 u;
        u.x = h2u(__floats2half2_rn(v[2*c].x * inv,   v[2*c].y * inv));
        u.y = h2u(__floats2half2_rn(v[2*c].z * inv,   v[2*c].w * inv));
        u.z = h2u(__floats2half2_rn(v[2*c+1].x * inv, v[2*c+1].y * inv));
        u.w = h2u(__floats2half2_rn(v[2*c+1].z * inv, v[2*c+1].w * inv));
        o16[c * 32 + lane] = u;
    }

    int lab = clampc(labels[row]);
    float lg = (lane < NCLS) ? logits[row * NCLS + lane] : -INFINITY;
    float m = lg;
#pragma unroll
    for (int o = 16; o; o >>= 1) m = fmaxf(m, __shfl_xor_sync(FULL, m, o));
    float p = (lane < NCLS) ? expf(lg - m) : 0.0f;
    float s = p;
#pragma unroll
    for (int o = 16; o; o >>= 1) s += __shfl_xor_sync(FULL, s, o);
    float lse = logf(s) + m;
    float target = __shfl_sync(FULL, lg, lab);
    if (lane == 0) wce[warp] = lse - target;
    __syncthreads();
    if (threadIdx.x == 0) {
        float c = 0.0f;
#pragma unroll
        for (int w = 0; w < 8; w++) c += wce[w];
        g_ce_part[blockIdx.x] = c;
    }
}

// ---------------- centroid sums -> atomic reduce into g_cents --------------
__global__ __launch_bounds__(256) void k_centsum(
    const float* __restrict__ emb,
    const int* __restrict__ labels)
{
    __shared__ float af[4 * NCLS * 256];
    int tid = threadIdx.x;
    int bx = blockIdx.x % 3;
    int by = blockIdx.x / 3;
    int col = bx * 256 + tid;
    int r0  = by * ROWS_PER_PART;

#pragma unroll
    for (int k = 0; k < 4 * NCLS; k++) af[k * 256 + tid] = 0.0f;

    const float* ecol = emb + col;
#pragma unroll 2
    for (int r = 0; r < ROWS_PER_PART; r += 4) {
#pragma unroll
        for (int qq = 0; qq < 4; qq++) {
            int rr = r0 + r + qq;
            int lab = clampc(labels[rr]);
            af[(qq * NCLS + lab) * 256 + tid] += ecol[(size_t)rr * DIM];
        }
    }

#pragma unroll
    for (int c = 0; c < NCLS; c++) {
        float s = af[(0 * NCLS + c) * 256 + tid] + af[(1 * NCLS + c) * 256 + tid]
                + af[(2 * NCLS + c) * 256 + tid] + af[(3 * NCLS + c) * 256 + tid];
        atomicAdd(&g_cents[c * DIM + col], s);
    }
}

// ---------------- TAML GEMM + TALS rider + last-block final combine --------
__device__ __forceinline__ void stage_tiles(
    uint32_t sb, uint32_t stoff, const __half* Ag, const __half* Bg, int kb, int tid)
{
    uint32_t aoff = stoff;
    uint32_t boff = stoff + BM * 128;
#pragma unroll
    for (int q = 0; q < 4; q++) {
        int f = tid + q * 256;
        int row = f >> 3, ch = f & 7;
        const __half* src = Ag + (size_t)row * DIM + kb + ch * 8;
        uint32_t dst = sb + aoff + row * 128 + (((uint32_t)(ch ^ (row & 7))) << 4);
        CPA16(dst, src);
    }
#pragma unroll
    for (int q = 0; q < 8; q++) {
        int f = tid + q * 256;
        int row = f >> 3, ch = f & 7;
        const __half* src = Bg + (size_t)row * DIM + kb + ch * 8;
        uint32_t dst = sb + boff + row * 128 + (((uint32_t)(ch ^ (row & 7))) << 4);
        CPA16(dst, src);
    }
}

__device__ __forceinline__ void load_frags(
    uint32_t ab, uint32_t bb, int ks, int warpM, int warpN, int lane,
    uint32_t a[4][4], uint32_t b[4][4])
{
#pragma unroll
    for (int mf = 0; mf < 4; mf++) {
        int arow = warpM * 64 + mf * 16 + ((lane >> 3) & 1) * 8 + (lane & 7);
        int kch = ks * 2 + (lane >> 4);
        uint32_t ad = ab + arow * 128 + (((uint32_t)(kch ^ (arow & 7))) << 4);
        LDSM4(a[mf][0], a[mf][1], a[mf][2], a[mf][3], ad);
    }
#pragma unroll
    for (int p = 0; p < 4; p++) {
        int col = warpN * 64 + p * 16 + (lane >> 4) * 8 + (lane & 7);
        int kch = ks * 2 + ((lane >> 3) & 1);
        uint32_t bd = bb + col * 128 + (((uint32_t)(kch ^ (col & 7))) << 4);
        LDSM4(b[p][0], b[p][1], b[p][2], b[p][3], bd);
    }
}

// tail executed by every block; last arrival does the final combine
__device__ __forceinline__ void arrive_and_maybe_finalize(
    char* sm, int tid, float* __restrict__ out)
{
    const unsigned FULL = 0xffffffffu;
    int* lastS = (int*)(sm + OFF_LAST);
    __threadfence();
    if (tid == 0) {
        int prev = atomicAdd(&g_arrive, 1);
        *lastS = (prev == NARRIVE - 1);
    }
    __syncthreads();
    if (!*lastS) return;

    int warp = tid >> 5, lane = tid & 31;
    float* redS = (float*)(sm + OFF_WRED);
    if (warp == 0) {
        float s = 0.0f;
        for (int i = lane; i < NCE_BLK; i += 32) s += g_ce_part[i];
#pragma unroll
        for (int o = 16; o; o >>= 1) s += __shfl_xor_sync(FULL, s, o);
        if (lane == 0) redS[0] = s;
    } else if (warp == 1) {
        float s = 0.0f;
        for (int i = lane; i < NCTA_TAML; i += 32) s += g_taml_part[i];
#pragma unroll
        for (int o = 16; o; o >>= 1) s += __shfl_xor_sync(FULL, s, o);
        if (lane == 0) redS[1] = s;
    }
    __syncthreads();
    if (tid == 0) {
        float taml = redS[1] / fmaxf(g_nvalid, 1.0f);
        float ce   = redS[0] / (float)BATCH;
        float tals = g_tals;
        out[0] = ce + 0.5f * tals + 0.5f * taml;
        out[1] = ce;
        out[2] = tals;
        out[3] = taml;
        g_arrive = 0;   // reset for next graph replay
    }
}

__global__ __launch_bounds__(256) void k_taml(
    const int* __restrict__ labels,
    const float* __restrict__ topo,
    float* __restrict__ out)
{
    extern __shared__ __align__(1024) char sm[];
    int tid = threadIdx.x;
    const unsigned FULL = 0xffffffffu;

    if (blockIdx.x == NCTA_TAML) {
        // ---------------- TALS block (runs in the GEMM's shadow) ----------
        float* sc    = (float*)(sm + TOFF_SC);
        float* ed    = (float*)(sm + TOFF_ED);
        float* wcnt  = (float*)(sm + TOFF_WCNT);
        float* cnts  = (float*)(sm + TOFF_CNTS);
        int warp = tid >> 5, lane = tid & 31;

        int cnt_acc[NCLS];
#pragma unroll
        for (int c = 0; c < NCLS; c++) cnt_acc[c] = 0;
        for (int q = 0; q < 16; q++) {
            int lb = clampc(labels[warp * 512 + q * 32 + lane]);
#pragma unroll
            for (int c = 0; c < NCLS; c++)
                cnt_acc[c] += __popc(__ballot_sync(FULL, lb == c));
        }
        if (lane == 0)
#pragma unroll
            for (int c = 0; c < NCLS; c++) wcnt[warp * NCLS + c] = (float)cnt_acc[c];
        if (tid < 128) ed[tid] = 0.0f;
        __syncthreads();
        if (tid < NCLS) {
            float s = 0.0f;
#pragma unroll
            for (int w = 0; w < 8; w++) s += wcnt[w * NCLS + tid];
            cnts[tid] = s;
        }
        __syncthreads();

        for (int idx = tid; idx < NCLS * DIM / 4; idx += 256) {
            float4 v = *(const float4*)(g_cents + idx * 4);
            int c = idx / (DIM / 4);
            float inv = __frcp_rn(fmaxf(cnts[c], 1.0f));
            *(float4*)(sc + idx * 4) = make_float4(v.x * inv, v.y * inv, v.z * inv, v.w * inv);
        }
        __syncthreads();

        for (int p = warp; p < NCLS * NCLS; p += 8) {
            int i = p / NCLS, j = p % NCLS;
            const float4* ci = (const float4*)(sc + i * DIM);
            const float4* cj = (const float4*)(sc + j * DIM);
            float s = 0.0f;
#pragma unroll
            for (int t = 0; t < DIM / 128; t++) {
                float4 a = ci[lane + 32 * t];
                float4 b = cj[lane + 32 * t];
                float dx = a.x - b.x, dy = a.y - b.y, dz = a.z - b.z, dw = a.w - b.w;
                s += dx * dx + dy * dy + dz * dz + dw * dw;
            }
#pragma unroll
            for (int o = 16; o; o >>= 1) s += __shfl_xor_sync(FULL, s, o);
            if (lane == 0) ed[p] = sqrtf(s + 1e-12f);
        }
        __syncthreads();

        if (warp == 0) {
            float m0 = fmaxf(ed[lane], fmaxf(ed[lane + 32], fmaxf(ed[lane + 64], ed[lane + 96])));
#pragma unroll
            for (int o = 16; o; o >>= 1) m0 = fmaxf(m0, __shfl_xor_sync(FULL, m0, o));
            float inv = 1.0f / (m0 + 1e-8f);
            float mse = 0.0f;
            for (int p = lane; p < NCLS * NCLS; p += 32) {
                float v = ed[p] * inv - topo[p];
                mse += v * v;
            }
#pragma unroll
            for (int o = 16; o; o >>= 1) mse += __shfl_xor_sync(FULL, mse, o);
            if (lane == 0) g_tals = mse / (float)(NCLS * NCLS);
        } else if (warp == 1 && lane == 0) {
            float s2 = 0.0f;
#pragma unroll
            for (int c = 0; c < NCLS; c++) s2 += cnts[c] * cnts[c];
            g_nvalid = (float)BATCH * (float)BATCH - s2;
        }
        __syncthreads();
        arrive_and_maybe_finalize(sm, tid, out);
        return;
    }

    // ---------------- GEMM blocks ----------------
    uint32_t sb = s2u(sm);
    int lane = tid & 31;
    int wid  = tid >> 5;
    int warpM = wid & 1;
    int warpN = wid >> 1;

    int bid = blockIdx.x;
    int c2 = 0;
    while (bid >= (2 * c2 + 2)) { bid -= (2 * c2 + 2); c2++; }
    int r = bid;
    int rowA0 = r * BM;
    int rowB0 = c2 * BN;

    float* sthrS = (float*)(sm + OFF_STHR);
    int*   lrowS = (int*)(sm + OFF_LROW);
    int*   lcolS = (int*)(sm + OFF_LCOL);
    float* wredS = (float*)(sm + OFF_WRED);
    if (tid < NCLS * NCLS) sthrS[tid] = 1.0f - topo[tid];
    if (tid < BM) lrowS[tid] = clampc(labels[rowA0 + tid]);
    lcolS[tid] = clampc(labels[rowB0 + tid]);

    const __half* Ag = g_enorm + (size_t)rowA0 * DIM;
    const __half* Bg = g_enorm + (size_t)rowB0 * DIM;

    float acc[4][8][4];
#pragma unroll
    for (int i = 0; i < 4; i++)
#pragma unroll
        for (int j = 0; j < 8; j++)
#pragma unroll
            for (int k = 0; k < 4; k++) acc[i][j][k] = 0.0f;

    stage_tiles(sb, 0 * STAGE_BYTES, Ag, Bg, 0 * BK, tid);
    CPCOMMIT();
    stage_tiles(sb, 1 * STAGE_BYTES, Ag, Bg, 1 * BK, tid);
    CPCOMMIT();

    for (int it = 0; it < NKIT; it++) {
        if (it == NKIT - 1) { CPWAIT(0); } else { CPWAIT(1); }
        __syncthreads();
        if (it + 2 < NKIT) {
            stage_tiles(sb, (uint32_t)((it + 2) % 3) * STAGE_BYTES, Ag, Bg, (it + 2) * BK, tid);
            CPCOMMIT();
        }

        uint32_t st = (uint32_t)(it % 3) * STAGE_BYTES;
        uint32_t ab = sb + st;
        uint32_t bb = sb + st + BM * 128;

        uint32_t a[2][4][4], b[2][4][4];
        load_frags(ab, bb, 0, warpM, warpN, lane, a[0], b[0]);
#pragma unroll
        for (int ks = 0; ks < 4; ks++) {
            int cur = ks & 1;
            if (ks < 3)
                load_frags(ab, bb, ks + 1, warpM, warpN, lane, a[cur ^ 1], b[cur ^ 1]);
#pragma unroll
            for (int mf = 0; mf < 4; mf++)
#pragma unroll
                for (int nf = 0; nf < 8; nf++) {
                    uint32_t b0 = b[cur][nf >> 1][(nf & 1) * 2];
                    uint32_t b1 = b[cur][nf >> 1][(nf & 1) * 2 + 1];
                    MMA_F16(acc[mf][nf], a[cur][mf], b0, b1);
                }
        }
    }
    __syncthreads();

    float lsum = 0.0f;
#pragma unroll
    for (int mf = 0; mf < 4; mf++) {
        int row0 = warpM * 64 + mf * 16 + (lane >> 2);
        int la0 = lrowS[row0];
        int la1 = lrowS[row0 + 8];
        int ig0 = rowA0 + row0;
#pragma unroll
        for (int nf = 0; nf < 8; nf++) {
            int col = warpN * 64 + nf * 8 + (lane & 3) * 2;
            int lb0 = lcolS[col], lb1 = lcolS[col + 1];
            int jg0 = rowB0 + col;
            if (jg0 > ig0 && la0 != lb0)
                lsum += fmaxf(acc[mf][nf][0] - sthrS[la0 * NCLS + lb0], 0.0f);
            if (jg0 + 1 > ig0 && la0 != lb1)
                lsum += fmaxf(acc[mf][nf][1] - sthrS[la0 * NCLS + lb1], 0.0f);
            if (jg0 > ig0 + 8 && la1 != lb0)
                lsum += fmaxf(acc[mf][nf][2] - sthrS[la1 * NCLS + lb0], 0.0f);
            if (jg0 + 1 > ig0 + 8 && la1 != lb1)
                lsum += fmaxf(acc[mf][nf][3] - sthrS[la1 * NCLS + lb1], 0.0f);
        }
    }
    lsum *= 2.0f;

#pragma unroll
    for (int o = 16; o; o >>= 1) lsum += __shfl_xor_sync(FULL, lsum, o);
    if (lane == 0) wredS[wid] = lsum;
    __syncthreads();
    if (tid == 0) {
        float t = 0.0f;
#pragma unroll
        for (int w = 0; w < 8; w++) t += wredS[w];
        g_taml_part[blockIdx.x] = t;
    }
    __syncthreads();
    arrive_and_maybe_finalize(sm, tid, out);
}

extern "C" void kernel_launch(void* const* d_in, const int* in_sizes, int n_in,
                              void* d_out, int out_size) {
    const float* logits = (const float*)d_in[0];
    const int*   labels = (const int*)d_in[1];
    const float* emb    = (const float*)d_in[2];
    const float* topo   = (const float*)d_in[3];
    float* out = (float*)d_out;

    cudaFuncSetAttribute(k_taml, cudaFuncAttributeMaxDynamicSharedMemorySize, DYN_SMEM);

    k_ce_norm<<<NCE_BLK, 256>>>(logits, labels, emb);               // 0
    k_centsum<<<NCS_BLK, 256>>>(emb, labels);                       // 1
    k_taml<<<NARRIVE, 256, DYN_SMEM>>>(labels, topo, out);          // 2 (GEMM+TALS+final)
}

// round 16
// speedup vs baseline: 1.5266x; 1.5266x over previous
#include <cuda_runtime.h>
#include <cuda_fp16.h>
#include <math.h>
#include <stdint.h>

#define BATCH 4096
#define DIM   768
#define NCLS  10

#define BM 128
#define BN 256
#define BK 64                 // 64 halves = 128B per row-chunk
#define NKIT (DIM / BK)       // 12
#define NCTA_TAML 272
#define NCE_BLK (BATCH / 8)   // 512
#define NPART 16
#define NCS_BLK (3 * NPART)   // 48
#define ROWS_PER_PART (BATCH / NPART)  // 256

// 3-stage smem pipeline: each stage = A(16KB) + B(32KB) = 48KB
#define STAGE_BYTES 49152
#define OFF_MISC (3 * STAGE_BYTES)
#define OFF_STHR (OFF_MISC)
#define OFF_LROW (OFF_MISC + 512)
#define OFF_LCOL (OFF_MISC + 1024)
#define OFF_WRED (OFF_MISC + 2048)
#define DYN_SMEM (OFF_MISC + 2112)     // 149568

// tals-block layout inside the same dynamic smem
#define TOFF_SC   0
#define TOFF_ED   30720
#define TOFF_WCNT 31232
#define TOFF_CNTS 31616
#define TOFF_RED  31680

__device__ __forceinline__ int clampc(int v) {
    return v < 0 ? 0 : (v >= NCLS ? NCLS - 1 : v);
}
__device__ __forceinline__ uint32_t s2u(const void* p) {
    uint32_t a;
    asm("{ .reg .u64 t; cvta.to.shared.u64 t, %1; cvt.u32.u64 %0, t; }" : "=r"(a) : "l"(p));
    return a;
}
__device__ __forceinline__ uint32_t h2u(__half2 h) {
    return *reinterpret_cast<uint32_t*>(&h);
}

#define LDSM4(r0, r1, r2, r3, addr) \
    asm volatile("ldmatrix.sync.aligned.m8n8.x4.shared.b16 {%0,%1,%2,%3}, [%4];" \
                 : "=r"(r0), "=r"(r1), "=r"(r2), "=r"(r3) : "r"(addr))

#define MMA_F16(d, a, b0, b1) \
    asm volatile("mma.sync.aligned.m16n8k16.row.col.f32.f16.f16.f32 " \
                 "{%0,%1,%2,%3},{%4,%5,%6,%7},{%8,%9},{%0,%1,%2,%3};" \
                 : "+f"((d)[0]), "+f"((d)[1]), "+f"((d)[2]), "+f"((d)[3]) \
                 : "r"((a)[0]), "r"((a)[1]), "r"((a)[2]), "r"((a)[3]), \
                   "r"(b0), "r"(b1))

#define CPA16(dst, src) \
    asm volatile("cp.async.cg.shared.global [%0], [%1], 16;" :: "r"(dst), "l"(src) : "memory")
#define CPCOMMIT() asm volatile("cp.async.commit_group;" ::: "memory")
#define CPWAIT(n)  asm volatile("cp.async.wait_group %0;" :: "n"(n) : "memory")

// ---------------- scratch ----------------
__device__ __half g_enorm[BATCH * DIM];
__device__ float g_cents[NCLS * DIM];
__device__ float g_ce_part[NCE_BLK];
__device__ volatile float g_taml_part[NCTA_TAML];
__device__ int   g_arrive;            // zero-init; reset to 0 by the combiner

// ---------------- CE + row normalization (+ block 0 zeroes g_cents) --------
__global__ __launch_bounds__(256) void k_ce_norm(
    const float* __restrict__ logits,
    const int* __restrict__ labels,
    const float* __restrict__ emb)
{
    __shared__ float wce[8];
    const unsigned FULL = 0xffffffffu;
    int warp = threadIdx.x >> 5;
    int lane = threadIdx.x & 31;
    int row  = blockIdx.x * 8 + warp;

    if (blockIdx.x == 0) {
        for (int i = threadIdx.x; i < NCLS * DIM; i += 256) g_cents[i] = 0.0f;
    }

    const float4* e4 = (const float4*)(emb + (size_t)row * DIM);
    float4 v[6];
    float ss = 0.0f;
#pragma unroll
    for (int c = 0; c < 3; c++) {
        v[2 * c]     = e4[c * 64 + lane * 2];
        v[2 * c + 1] = e4[c * 64 + lane * 2 + 1];
        ss += v[2*c].x * v[2*c].x + v[2*c].y * v[2*c].y
            + v[2*c].z * v[2*c].z + v[2*c].w * v[2*c].w
            + v[2*c+1].x * v[2*c+1].x + v[2*c+1].y * v[2*c+1].y
            + v[2*c+1].z * v[2*c+1].z + v[2*c+1].w * v[2*c+1].w;
    }
#pragma unroll
    for (int o = 16; o; o >>= 1) ss += __shfl_xor_sync(FULL, ss, o);
    float inv = 1.0f / fmaxf(sqrtf(ss), 1e-12f);

    uint4* o16 = (uint4*)(g_enorm + (size_t)row * DIM);
#pragma unroll
    for (int c = 0; c < 3; c++) {
        uint4 u;
        u.x = h2u(__floats2half2_rn(v[2*c].x * inv,   v[2*c].y * inv));
        u.y = h2u(__floats2half2_rn(v[2*c].z * inv,   v[2*c].w * inv));
        u.z = h2u(__floats2half2_rn(v[2*c+1].x * inv, v[2*c+1].y * inv));
        u.w = h2u(__floats2half2_rn(v[2*c+1].z * inv, v[2*c+1].w * inv));
        o16[c * 32 + lane] = u;
    }

    int lab = clampc(labels[row]);
    float lg = (lane < NCLS) ? logits[row * NCLS + lane] : -INFINITY;
    float m = lg;
#pragma unroll
    for (int o = 16; o; o >>= 1) m = fmaxf(m, __shfl_xor_sync(FULL, m, o));
    float p = (lane < NCLS) ? expf(lg - m) : 0.0f;
    float s = p;
#pragma unroll
    for (int o = 16; o; o >>= 1) s += __shfl_xor_sync(FULL, s, o);
    float lse = logf(s) + m;
    float target = __shfl_sync(FULL, lg, lab);
    if (lane == 0) wce[warp] = lse - target;
    __syncthreads();
    if (threadIdx.x == 0) {
        float c = 0.0f;
#pragma unroll
        for (int w = 0; w < 8; w++) c += wce[w];
        g_ce_part[blockIdx.x] = c;
    }
}

// ---------------- centroid sums -> atomic reduce into g_cents --------------
__global__ __launch_bounds__(256) void k_centsum(
    const float* __restrict__ emb,
    const int* __restrict__ labels)
{
    __shared__ float af[4 * NCLS * 256];
    int tid = threadIdx.x;
    int bx = blockIdx.x % 3;
    int by = blockIdx.x / 3;
    int col = bx * 256 + tid;
    int r0  = by * ROWS_PER_PART;

#pragma unroll
    for (int k = 0; k < 4 * NCLS; k++) af[k * 256 + tid] = 0.0f;

    const float* ecol = emb + col;
#pragma unroll 2
    for (int r = 0; r < ROWS_PER_PART; r += 4) {
#pragma unroll
        for (int qq = 0; qq < 4; qq++) {
            int rr = r0 + r + qq;
            int lab = clampc(labels[rr]);
            af[(qq * NCLS + lab) * 256 + tid] += ecol[(size_t)rr * DIM];
        }
    }

#pragma unroll
    for (int c = 0; c < NCLS; c++) {
        float s = af[(0 * NCLS + c) * 256 + tid] + af[(1 * NCLS + c) * 256 + tid]
                + af[(2 * NCLS + c) * 256 + tid] + af[(3 * NCLS + c) * 256 + tid];
        atomicAdd(&g_cents[c * DIM + col], s);
    }
}

// ---------------- TAML GEMM + TALS/combiner rider block --------------------
__device__ __forceinline__ void stage_tiles(
    uint32_t sb, uint32_t stoff, const __half* Ag, const __half* Bg, int kb, int tid)
{
    uint32_t aoff = stoff;
    uint32_t boff = stoff + BM * 128;
#pragma unroll
    for (int q = 0; q < 4; q++) {
        int f = tid + q * 256;
        int row = f >> 3, ch = f & 7;
        const __half* src = Ag + (size_t)row * DIM + kb + ch * 8;
        uint32_t dst = sb + aoff + row * 128 + (((uint32_t)(ch ^ (row & 7))) << 4);
        CPA16(dst, src);
    }
#pragma unroll
    for (int q = 0; q < 8; q++) {
        int f = tid + q * 256;
        int row = f >> 3, ch = f & 7;
        const __half* src = Bg + (size_t)row * DIM + kb + ch * 8;
        uint32_t dst = sb + boff + row * 128 + (((uint32_t)(ch ^ (row & 7))) << 4);
        CPA16(dst, src);
    }
}

__device__ __forceinline__ void load_frags(
    uint32_t ab, uint32_t bb, int ks, int warpM, int warpN, int lane,
    uint32_t a[4][4], uint32_t b[4][4])
{
#pragma unroll
    for (int mf = 0; mf < 4; mf++) {
        int arow = warpM * 64 + mf * 16 + ((lane >> 3) & 1) * 8 + (lane & 7);
        int kch = ks * 2 + (lane >> 4);
        uint32_t ad = ab + arow * 128 + (((uint32_t)(kch ^ (arow & 7))) << 4);
        LDSM4(a[mf][0], a[mf][1], a[mf][2], a[mf][3], ad);
    }
#pragma unroll
    for (int p = 0; p < 4; p++) {
        int col = warpN * 64 + p * 16 + (lane >> 4) * 8 + (lane & 7);
        int kch = ks * 2 + ((lane >> 3) & 1);
        uint32_t bd = bb + col * 128 + (((uint32_t)(kch ^ (col & 7))) << 4);
        LDSM4(b[p][0], b[p][1], b[p][2], b[p][3], bd);
    }
}

__global__ __launch_bounds__(256) void k_taml(
    const int* __restrict__ labels,
    const float* __restrict__ topo,
    float* __restrict__ out)
{
    extern __shared__ __align__(1024) char sm[];
    int tid = threadIdx.x;
    const unsigned FULL = 0xffffffffu;

    if (blockIdx.x == NCTA_TAML) {
        // ------- TALS + final-combine rider (runs in the GEMM's shadow) ----
        float* sc    = (float*)(sm + TOFF_SC);
        float* ed    = (float*)(sm + TOFF_ED);
        float* wcnt  = (float*)(sm + TOFF_WCNT);
        float* cnts  = (float*)(sm + TOFF_CNTS);
        float* redS  = (float*)(sm + TOFF_RED);   // [0]=tals [1]=nvalid [2]=ce [3]=taml
        int warp = tid >> 5, lane = tid & 31;

        int cnt_acc[NCLS];
#pragma unroll
        for (int c = 0; c < NCLS; c++) cnt_acc[c] = 0;
        for (int q = 0; q < 16; q++) {
            int lb = clampc(labels[warp * 512 + q * 32 + lane]);
#pragma unroll
            for (int c = 0; c < NCLS; c++)
                cnt_acc[c] += __popc(__ballot_sync(FULL, lb == c));
        }
        if (lane == 0)
#pragma unroll
            for (int c = 0; c < NCLS; c++) wcnt[warp * NCLS + c] = (float)cnt_acc[c];
        if (tid < 128) ed[tid] = 0.0f;
        __syncthreads();
        if (tid < NCLS) {
            float s = 0.0f;
#pragma unroll
            for (int w = 0; w < 8; w++) s += wcnt[w * NCLS + tid];
            cnts[tid] = s;
        }
        __syncthreads();

        for (int idx = tid; idx < NCLS * DIM / 4; idx += 256) {
            float4 v = *(const float4*)(g_cents + idx * 4);
            int c = idx / (DIM / 4);
            float inv = __frcp_rn(fmaxf(cnts[c], 1.0f));
            *(float4*)(sc + idx * 4) = make_float4(v.x * inv, v.y * inv, v.z * inv, v.w * inv);
        }
        __syncthreads();

        for (int p = warp; p < NCLS * NCLS; p += 8) {
            int i = p / NCLS, j = p % NCLS;
            const float4* ci = (const float4*)(sc + i * DIM);
            const float4* cj = (const float4*)(sc + j * DIM);
            float s = 0.0f;
#pragma unroll
            for (int t = 0; t < DIM / 128; t++) {
                float4 a = ci[lane + 32 * t];
                float4 b = cj[lane + 32 * t];
                float dx = a.x - b.x, dy = a.y - b.y, dz = a.z - b.z, dw = a.w - b.w;
                s += dx * dx + dy * dy + dz * dz + dw * dw;
            }
#pragma unroll
            for (int o = 16; o; o >>= 1) s += __shfl_xor_sync(FULL, s, o);
            if (lane == 0) ed[p] = sqrtf(s + 1e-12f);
        }
        __syncthreads();

        if (warp == 0) {        // tals
            float m0 = fmaxf(ed[lane], fmaxf(ed[lane + 32], fmaxf(ed[lane + 64], ed[lane + 96])));
#pragma unroll
            for (int o = 16; o; o >>= 1) m0 = fmaxf(m0, __shfl_xor_sync(FULL, m0, o));
            float inv = 1.0f / (m0 + 1e-8f);
            float mse = 0.0f;
            for (int p = lane; p < NCLS * NCLS; p += 32) {
                float v = ed[p] * inv - topo[p];
                mse += v * v;
            }
#pragma unroll
            for (int o = 16; o; o >>= 1) mse += __shfl_xor_sync(FULL, mse, o);
            if (lane == 0) redS[0] = mse / (float)(NCLS * NCLS);
        } else if (warp == 1) { // nvalid + ce partial sum
            if (lane == 0) {
                float s2 = 0.0f;
#pragma unroll
                for (int c = 0; c < NCLS; c++) s2 += cnts[c] * cnts[c];
                redS[1] = (float)BATCH * (float)BATCH - s2;
            }
        } else if (warp == 2) { // ce sum (same pattern as old k_final warp 0)
            float s = 0.0f;
            for (int i = lane; i < NCE_BLK; i += 32) s += g_ce_part[i];
#pragma unroll
            for (int o = 16; o; o >>= 1) s += __shfl_xor_sync(FULL, s, o);
            if (lane == 0) redS[2] = s;
        }

        // ---- wait for all GEMM blocks, then combine ----
        if (tid == 0) {
            while (atomicAdd(&g_arrive, 0) < NCTA_TAML) __nanosleep(200);
        }
        __syncthreads();
        __threadfence();   // acquire view of g_taml_part (executed by rider block only)

        if (warp == 0) {   // taml sum (same pattern as old k_final warp 1)
            float s = 0.0f;
            for (int i = lane; i < NCTA_TAML; i += 32) s += g_taml_part[i];
#pragma unroll
            for (int o = 16; o; o >>= 1) s += __shfl_xor_sync(FULL, s, o);
            if (lane == 0) redS[3] = s;
        }
        __syncthreads();
        if (tid == 0) {
            float taml = redS[3] / fmaxf(redS[1], 1.0f);
            float ce   = redS[2] / (float)BATCH;
            float tals = redS[0];
            out[0] = ce + 0.5f * tals + 0.5f * taml;
            out[1] = ce;
            out[2] = tals;
            out[3] = taml;
            __threadfence();
            g_arrive = 0;   // reset for next graph replay
        }
        return;
    }

    // ---------------- GEMM blocks (identical to R14) ----------------
    uint32_t sb = s2u(sm);
    int lane = tid & 31;
    int wid  = tid >> 5;
    int warpM = wid & 1;
    int warpN = wid >> 1;

    int bid = blockIdx.x;
    int c2 = 0;
    while (bid >= (2 * c2 + 2)) { bid -= (2 * c2 + 2); c2++; }
    int r = bid;
    int rowA0 = r * BM;
    int rowB0 = c2 * BN;

    float* sthrS = (float*)(sm + OFF_STHR);
    int*   lrowS = (int*)(sm + OFF_LROW);
    int*   lcolS = (int*)(sm + OFF_LCOL);
    float* wredS = (float*)(sm + OFF_WRED);
    if (tid < NCLS * NCLS) sthrS[tid] = 1.0f - topo[tid];
    if (tid < BM) lrowS[tid] = clampc(labels[rowA0 + tid]);
    lcolS[tid] = clampc(labels[rowB0 + tid]);

    const __half* Ag = g_enorm + (size_t)rowA0 * DIM;
    const __half* Bg = g_enorm + (size_t)rowB0 * DIM;

    float acc[4][8][4];
#pragma unroll
    for (int i = 0; i < 4; i++)
#pragma unroll
        for (int j = 0; j < 8; j++)
#pragma unroll
            for (int k = 0; k < 4; k++) acc[i][j][k] = 0.0f;

    stage_tiles(sb, 0 * STAGE_BYTES, Ag, Bg, 0 * BK, tid);
    CPCOMMIT();
    stage_tiles(sb, 1 * STAGE_BYTES, Ag, Bg, 1 * BK, tid);
    CPCOMMIT();

    for (int it = 0; it < NKIT; it++) {
        if (it == NKIT - 1) { CPWAIT(0); } else { CPWAIT(1); }
        __syncthreads();
        if (it + 2 < NKIT) {
            stage_tiles(sb, (uint32_t)((it + 2) % 3) * STAGE_BYTES, Ag, Bg, (it + 2) * BK, tid);
            CPCOMMIT();
        }

        uint32_t st = (uint32_t)(it % 3) * STAGE_BYTES;
        uint32_t ab = sb + st;
        uint32_t bb = sb + st + BM * 128;

        uint32_t a[2][4][4], b[2][4][4];
        load_frags(ab, bb, 0, warpM, warpN, lane, a[0], b[0]);
#pragma unroll
        for (int ks = 0; ks < 4; ks++) {
            int cur = ks & 1;
            if (ks < 3)
                load_frags(ab, bb, ks + 1, warpM, warpN, lane, a[cur ^ 1], b[cur ^ 1]);
#pragma unroll
            for (int mf = 0; mf < 4; mf++)
#pragma unroll
                for (int nf = 0; nf < 8; nf++) {
                    uint32_t b0 = b[cur][nf >> 1][(nf & 1) * 2];
                    uint32_t b1 = b[cur][nf >> 1][(nf & 1) * 2 + 1];
                    MMA_F16(acc[mf][nf], a[cur][mf], b0, b1);
                }
        }
    }
    __syncthreads();

    float lsum = 0.0f;
#pragma unroll
    for (int mf = 0; mf < 4; mf++) {
        int row0 = warpM * 64 + mf * 16 + (lane >> 2);
        int la0 = lrowS[row0];
        int la1 = lrowS[row0 + 8];
        int ig0 = rowA0 + row0;
#pragma unroll
        for (int nf = 0; nf < 8; nf++) {
            int col = warpN * 64 + nf * 8 + (lane & 3) * 2;
            int lb0 = lcolS[col], lb1 = lcolS[col + 1];
            int jg0 = rowB0 + col;
            if (jg0 > ig0 && la0 != lb0)
                lsum += fmaxf(acc[mf][nf][0] - sthrS[la0 * NCLS + lb0], 0.0f);
            if (jg0 + 1 > ig0 && la0 != lb1)
                lsum += fmaxf(acc[mf][nf][1] - sthrS[la0 * NCLS + lb1], 0.0f);
            if (jg0 > ig0 + 8 && la1 != lb0)
                lsum += fmaxf(acc[mf][nf][2] - sthrS[la1 * NCLS + lb0], 0.0f);
            if (jg0 + 1 > ig0 + 8 && la1 != lb1)
                lsum += fmaxf(acc[mf][nf][3] - sthrS[la1 * NCLS + lb1], 0.0f);
        }
    }
    lsum *= 2.0f;

#pragma unroll
    for (int o = 16; o; o >>= 1) lsum += __shfl_xor_sync(FULL, lsum, o);
    if (lane == 0) wredS[wid] = lsum;
    __syncthreads();
    if (tid == 0) {
        float t = 0.0f;
#pragma unroll
        for (int w = 0; w < 8; w++) t += wredS[w];
        g_taml_part[blockIdx.x] = t;
        __threadfence();                 // single-thread fence: order the store
        atomicAdd(&g_arrive, 1);
    }
}

extern "C" void kernel_launch(void* const* d_in, const int* in_sizes, int n_in,
                              void* d_out, int out_size) {
    const float* logits = (const float*)d_in[0];
    const int*   labels = (const int*)d_in[1];
    const float* emb    = (const float*)d_in[2];
    const float* topo   = (const float*)d_in[3];
    float* out = (float*)d_out;

    cudaFuncSetAttribute(k_taml, cudaFuncAttributeMaxDynamicSharedMemorySize, DYN_SMEM);

    k_ce_norm<<<NCE_BLK, 256>>>(logits, labels, emb);               // 0
    k_centsum<<<NCS_BLK, 256>>>(emb, labels);                       // 1
    k_taml<<<NCTA_TAML + 1, 256, DYN_SMEM>>>(labels, topo, out);    // 2 (GEMM+TALS+combine)
}